// round 2
// baseline (speedup 1.0000x reference)
#include <cuda_runtime.h>
#include <cuda_bf16.h>
#include <math.h>

#define NN   2048      // num nodes
#define CD   512       // input channels
#define DD   128       // embed dim
#define KP   1024      // pooled nodes
#define NW   64        // bit words per row (2048/32)

// ---------------- scratch (device globals; no runtime allocation) ----------------
__device__ float    g_FE [NN * 256];      // cols 0-127 teacher f_et, 128-255 student f_es
__device__ float    g_A  [NN * NN];       // binary adjacency as f32
__device__ unsigned g_Abits[NN * NW];     // bit-packed adjacency rows
__device__ float    g_dinv[NN];
__device__ float    g_S  [NN * 256];      // prescaled H (shared scratch, also pooled)
__device__ float    g_H1 [NN * 256];
__device__ float    g_H2 [NN * 256];
__device__ float    g_FG [NN * 256];      // f_gt | f_gs
__device__ float    g_G  [NN * NN];       // NCE gram
__device__ float    g_scores[NN];
__device__ int      g_idx [KP];
__device__ float    g_vals[KP];
__device__ float    g_NH [KP * 256];      // new_ht | new_hs
__device__ float    g_Ap [KP * KP];
__device__ float    g_dinvp[KP];
__device__ float    g_Hp1[KP * 256];
__device__ float    g_FP [KP * 256];      // f_pt | f_ps
__device__ float    g_Gp [KP * KP];
__device__ float    g_cgs[NN], g_cgt[NN], g_cps[KP], g_cpt[KP];

// ---------------- 1) embed: l2norm(x @ W_embed + b) ----------------
// grid (2048, 2): y==0 -> teacher(ft) into cols 0-127 ; y==1 -> student(fs) into 128-255
__global__ void embed_kernel(const float* __restrict__ fs, const float* __restrict__ ft,
                             const float* __restrict__ W, const float* __restrict__ b) {
    int row = blockIdx.x, br = blockIdx.y, d = threadIdx.x;
    const float* x = (br == 0 ? ft : fs) + (size_t)row * CD;
    __shared__ float xs[CD];
    __shared__ float red[DD];
    for (int k = d; k < CD; k += DD) xs[k] = x[k];
    __syncthreads();
    float acc = b[d];
#pragma unroll 8
    for (int k = 0; k < CD; k++) acc = fmaf(xs[k], W[k * DD + d], acc);
    red[d] = acc * acc;
    __syncthreads();
    for (int s = 64; s > 0; s >>= 1) { if (d < s) red[d] += red[d + s]; __syncthreads(); }
    float inv = 1.0f / sqrtf(red[0]);
    g_FE[row * 256 + br * DD + d] = acc * inv;
}

// ---------------- 2) gram of 128-dim rows ----------------
// mode 0: A = (f_et . f_et^T > 0)  (writes g_A float + g_Abits)
// mode 1: G  = f_gt . f_gs^T   (g_FG cols 0-127 vs 128-255)
// mode 2: Gp = f_pt . f_ps^T   (g_FP)
__global__ void gram_kernel(int mode, int n) {
    const float* Lb; const float* Rb; float* outF;
    if      (mode == 0) { Lb = g_FE;       Rb = g_FE;       outF = g_A;  }
    else if (mode == 1) { Lb = g_FG;       Rb = g_FG + 128; outF = g_G;  }
    else                { Lb = g_FP;       Rb = g_FP + 128; outF = g_Gp; }
    __shared__ float Ls[32][129];
    __shared__ float Rs[32][129];
    int tx = threadIdx.x, ty = threadIdx.y;
    int tid = ty * 32 + tx;
    int i0 = blockIdx.y * 32, j0 = blockIdx.x * 32;
    for (int e = tid; e < 32 * 128; e += 1024) {
        int r = e >> 7, c = e & 127;
        Ls[r][c] = Lb[(i0 + r) * 256 + c];
        Rs[r][c] = Rb[(j0 + r) * 256 + c];
    }
    __syncthreads();
    float acc = 0.f;
#pragma unroll
    for (int k = 0; k < 128; k++) acc = fmaf(Ls[ty][k], Rs[tx][k], acc);
    int i = i0 + ty, j = j0 + tx;
    if (mode == 0) {
        bool p = acc > 0.0f;
        outF[i * n + j] = p ? 1.0f : 0.0f;
        unsigned w = __ballot_sync(0xffffffffu, p);
        if (tx == 0) g_Abits[i * NW + (j0 >> 5)] = w;
    } else {
        outF[i * n + j] = acc;
    }
}

// ---------------- 3) degree + dinv from popcount ----------------
__global__ void deg_kernel() {
    int i = blockIdx.x * blockDim.x + threadIdx.x;
    if (i >= NN) return;
    unsigned s = 0;
#pragma unroll
    for (int w = 0; w < NW; w++) s += __popc(g_Abits[i * NW + w]);
    g_dinv[i] = 1.0f / sqrtf((float)s);
}

// ---------------- 4) row prescale into g_S ----------------
// mode 0: g_FE*dinv  mode 1: g_H1*dinv  mode 2: g_NH*dinvp
__global__ void scale_kernel(int mode, int rows) {
    int idx = blockIdx.x * blockDim.x + threadIdx.x;
    if (idx >= rows * 256) return;
    const float* src; const float* sc;
    if      (mode == 0) { src = g_FE; sc = g_dinv;  }
    else if (mode == 1) { src = g_H1; sc = g_dinv;  }
    else                { src = g_NH; sc = g_dinvp; }
    g_S[idx] = src[idx] * sc[idx >> 8];
}

// ---------------- 5) SGEMM  C = diag(rs) * (A @ g_S) ----------------
// mode 0: g_A @ g_S -> g_H1 (rs=g_dinv) ; 1: -> g_H2 ; 2: g_Ap @ g_S -> g_Hp1 (rs=g_dinvp)
__global__ void __launch_bounds__(256) sgemm_kernel(int M, int N, int K, int mode) {
    const float* A; const float* B; float* C; const float* rs;
    if      (mode == 0) { A = g_A;  B = g_S; C = g_H1;  rs = g_dinv;  }
    else if (mode == 1) { A = g_A;  B = g_S; C = g_H2;  rs = g_dinv;  }
    else                { A = g_Ap; B = g_S; C = g_Hp1; rs = g_dinvp; }
    __shared__ float As[16][65];
    __shared__ float Bs[16][64];
    int tid = threadIdx.x;
    int tx = tid & 15, ty = tid >> 4;           // 16x16 threads, 4x4 micro-tile
    int bx = blockIdx.x, by = blockIdx.y;
    float acc[4][4] = {};
    int am = tid >> 2, akq = (tid & 3) << 2;    // A-tile load mapping
    int bk = tid >> 4, bnq = (tid & 15) << 2;   // B-tile load mapping
    for (int k0 = 0; k0 < K; k0 += 16) {
        float4 av = *(const float4*)&A[(size_t)(by * 64 + am) * K + k0 + akq];
        As[akq + 0][am] = av.x; As[akq + 1][am] = av.y;
        As[akq + 2][am] = av.z; As[akq + 3][am] = av.w;
        float4 bv = *(const float4*)&B[(size_t)(k0 + bk) * N + bx * 64 + bnq];
        *(float4*)&Bs[bk][bnq] = bv;
        __syncthreads();
#pragma unroll
        for (int k = 0; k < 16; k++) {
            float a[4];
#pragma unroll
            for (int i = 0; i < 4; i++) a[i] = As[k][ty * 4 + i];
            float4 b4 = *(float4*)&Bs[k][tx * 4];
            float bb[4] = { b4.x, b4.y, b4.z, b4.w };
#pragma unroll
            for (int i = 0; i < 4; i++)
#pragma unroll
                for (int j = 0; j < 4; j++) acc[i][j] = fmaf(a[i], bb[j], acc[i][j]);
        }
        __syncthreads();
    }
#pragma unroll
    for (int i = 0; i < 4; i++) {
        int r = by * 64 + ty * 4 + i;
        float rv = rs[r];
        float4 v = make_float4(acc[i][0] * rv, acc[i][1] * rv, acc[i][2] * rv, acc[i][3] * rv);
        *(float4*)&C[(size_t)r * N + bx * 64 + tx * 4] = v;
    }
}

// ---------------- 6) TAGConv linear + l2norm ----------------
// mode 0: [FE|H1|H2](384) @ W_gnn -> g_FG ; mode 1: [NH|Hp1](256) @ W_gnnp -> g_FP
__global__ void taglin_kernel(int mode, const float* __restrict__ W, const float* __restrict__ b) {
    int row = blockIdx.x, br = blockIdx.y, d = threadIdx.x;
    int off = row * 256 + br * 128;
    __shared__ float f[384];
    __shared__ float red[128];
    int nparts;
    if (mode == 0) { f[d] = g_FE[off + d]; f[128 + d] = g_H1[off + d]; f[256 + d] = g_H2[off + d]; nparts = 3; }
    else           { f[d] = g_NH[off + d]; f[128 + d] = g_Hp1[off + d]; nparts = 2; }
    __syncthreads();
    float acc = b[d];
    int K = nparts * 128;
#pragma unroll 8
    for (int k = 0; k < K; k++) acc = fmaf(f[k], W[k * 128 + d], acc);
    red[d] = acc * acc;
    __syncthreads();
    for (int s = 64; s > 0; s >>= 1) { if (d < s) red[d] += red[d + s]; __syncthreads(); }
    float inv = 1.0f / sqrtf(red[0]);
    float* out = (mode == 0) ? g_FG : g_FP;
    out[off + d] = acc * inv;
}

// ---------------- 7) NCE row/col logsumexp contributions ----------------
// contrib[i] = logsumexp(row_i) - pos_i/T where row = {pos/T} U {G[i,j]/T, diag->-10/T}
// mode 0: G rows -> g_cgs ; 1: G cols -> g_cgt ; 2: Gp rows -> g_cps ; 3: Gp cols -> g_cpt
__global__ void lse_kernel(int mode) {
    const float* G; float* contrib; int n; bool col;
    if      (mode == 0) { G = g_G;  contrib = g_cgs; n = NN; col = false; }
    else if (mode == 1) { G = g_G;  contrib = g_cgt; n = NN; col = true;  }
    else if (mode == 2) { G = g_Gp; contrib = g_cps; n = KP; col = false; }
    else                { G = g_Gp; contrib = g_cpt; n = KP; col = true;  }
    const float invT = 14.285714285714286f;   // 1/0.07
    int i = blockIdx.x, t = threadIdx.x;
    float pos = G[i * n + i];
    float pm = pos * invT;
    __shared__ float red[256];
    float lmax = -3.402823e38f;
    for (int j = t; j < n; j += 256) {
        if (j == i) continue;
        float g = col ? G[j * n + i] : G[i * n + j];
        lmax = fmaxf(lmax, g);
    }
    red[t] = lmax;
    __syncthreads();
    for (int s = 128; s > 0; s >>= 1) { if (t < s) red[t] = fmaxf(red[t], red[t + s]); __syncthreads(); }
    float M = fmaxf(red[0] * invT, fmaxf(pm, -10.0f * invT));
    __syncthreads();
    float ls = 0.f;
    for (int j = t; j < n; j += 256) {
        if (j == i) continue;
        float g = col ? G[j * n + i] : G[i * n + j];
        ls += expf(g * invT - M);
    }
    red[t] = ls;
    __syncthreads();
    for (int s = 128; s > 0; s >>= 1) { if (t < s) red[t] += red[t + s]; __syncthreads(); }
    if (t == 0) {
        float S = red[0] + expf(pm - M) + expf(-10.0f * invT - M);
        contrib[i] = M + logf(S) - pm;
    }
}

// ---------------- 8) pooling scores ----------------
__global__ void scores_kernel(const float* __restrict__ Wp, const float* __restrict__ bp) {
    int i = blockIdx.x * blockDim.x + threadIdx.x;
    if (i >= NN) return;
    float acc = bp[0];
#pragma unroll 8
    for (int d = 0; d < 128; d++) acc = fmaf(g_FG[i * 256 + d], Wp[d], acc);
    g_scores[i] = 1.0f / (1.0f + expf(-acc));
}

// ---------------- 9) top-1024 of 2048 via one-block bitonic sort ----------------
__global__ void __launch_bounds__(1024) topk_kernel() {
    __shared__ float key[NN];
    __shared__ int   val[NN];
    int t = threadIdx.x;
    key[t]        = g_scores[t];        val[t]        = t;
    key[t + 1024] = g_scores[t + 1024]; val[t + 1024] = t + 1024;
    __syncthreads();
    for (int size = 2; size <= NN; size <<= 1) {
        for (int stride = size >> 1; stride > 0; stride >>= 1) {
            for (int half = 0; half < 2; half++) {
                int e = t + half * 1024;
                int j = e ^ stride;
                if (j > e) {
                    bool desc = ((e & size) == 0);
                    float ke = key[e], kj = key[j];
                    bool sw = desc ? (ke < kj) : (ke > kj);
                    if (sw) {
                        key[e] = kj; key[j] = ke;
                        int ve = val[e]; val[e] = val[j]; val[j] = ve;
                    }
                }
            }
            __syncthreads();
        }
    }
    if (t < KP) { g_idx[t] = val[t]; g_vals[t] = key[t]; }
}

// ---------------- 10) gather + score-scale pooled features ----------------
__global__ void gather_kernel() {
    int a = blockIdx.x, c = threadIdx.x;
    g_NH[a * 256 + c] = g_FG[g_idx[a] * 256 + c] * g_vals[a];
}

// ---------------- 11) pooled adjacency: Ap[a,b] = (bits[idx_a] & bits[idx_b]) != 0 ----------------
__global__ void ap_kernel() {
    __shared__ unsigned La[32][NW];
    __shared__ unsigned Lb[32][NW];
    int tx = threadIdx.x, ty = threadIdx.y;
    int tid = ty * 32 + tx;
    for (int e = tid; e < 32 * NW; e += 1024) {
        int r = e >> 6, w = e & 63;
        La[r][w] = g_Abits[(size_t)g_idx[blockIdx.y * 32 + r] * NW + w];
        Lb[r][w] = g_Abits[(size_t)g_idx[blockIdx.x * 32 + r] * NW + w];
    }
    __syncthreads();
    unsigned any = 0;
#pragma unroll
    for (int w = 0; w < NW; w++) any |= (La[ty][w] & Lb[tx][w]);
    g_Ap[(blockIdx.y * 32 + ty) * KP + blockIdx.x * 32 + tx] = any ? 1.0f : 0.0f;
}

// ---------------- 12) pooled degree ----------------
__global__ void degp_kernel() {
    int i = blockIdx.x, t = threadIdx.x;
    __shared__ float red[256];
    float s = 0.f;
    for (int j = t; j < KP; j += 256) s += g_Ap[i * KP + j];
    red[t] = s;
    __syncthreads();
    for (int st = 128; st > 0; st >>= 1) { if (t < st) red[t] += red[t + st]; __syncthreads(); }
    if (t == 0) g_dinvp[i] = 1.0f / sqrtf(red[0]);
}

// ---------------- 13) final deterministic reduce ----------------
__global__ void __launch_bounds__(1024) finalize_kernel(float* out) {
    __shared__ float red[1024];
    int t = threadIdx.x;
    float v = (g_cgs[t] + g_cgs[t + 1024] + g_cgt[t] + g_cgt[t + 1024]) * (1.0f / 2048.0f)
            + (g_cps[t] + g_cpt[t]) * (1.0f / 1024.0f);
    red[t] = v;
    __syncthreads();
    for (int s = 512; s > 0; s >>= 1) { if (t < s) red[t] += red[t + s]; __syncthreads(); }
    if (t == 0) out[0] = red[0];
}

// ---------------- launch ----------------
extern "C" void kernel_launch(void* const* d_in, const int* in_sizes, int n_in,
                              void* d_out, int out_size) {
    const float* fs    = (const float*)d_in[0];
    const float* ft    = (const float*)d_in[1];
    const float* We    = (const float*)d_in[2];
    const float* be    = (const float*)d_in[3];
    const float* Wg    = (const float*)d_in[4];
    const float* bg    = (const float*)d_in[5];
    const float* Wp    = (const float*)d_in[6];
    const float* bp    = (const float*)d_in[7];
    const float* Wgp   = (const float*)d_in[8];
    const float* bgp   = (const float*)d_in[9];
    float* out = (float*)d_out;

    // embed both branches
    embed_kernel<<<dim3(NN, 2), 128>>>(fs, ft, We, be);
    // adjacency (float + bits) from teacher features
    gram_kernel<<<dim3(NN / 32, NN / 32), dim3(32, 32)>>>(0, NN);
    deg_kernel<<<NN / 256, 256>>>();
    // hop 1 and hop 2 (teacher+student together, 256 cols)
    scale_kernel<<<(NN * 256) / 256, 256>>>(0, NN);
    sgemm_kernel<<<dim3(256 / 64, NN / 64), 256>>>(NN, 256, NN, 0);
    scale_kernel<<<(NN * 256) / 256, 256>>>(1, NN);
    sgemm_kernel<<<dim3(256 / 64, NN / 64), 256>>>(NN, 256, NN, 1);
    // TAGConv linear + l2norm
    taglin_kernel<<<dim3(NN, 2), 128>>>(0, Wg, bg);
    // graph-level NCE
    gram_kernel<<<dim3(NN / 32, NN / 32), dim3(32, 32)>>>(1, NN);
    lse_kernel<<<NN, 256>>>(0);
    lse_kernel<<<NN, 256>>>(1);
    // pooling
    scores_kernel<<<NN / 256, 256>>>(Wp, bp);
    topk_kernel<<<1, 1024>>>();
    gather_kernel<<<KP, 256>>>();
    ap_kernel<<<dim3(KP / 32, KP / 32), dim3(32, 32)>>>();
    degp_kernel<<<KP, 256>>>();
    // pooled TAGConv (k=1)
    scale_kernel<<<(KP * 256) / 256, 256>>>(2, KP);
    sgemm_kernel<<<dim3(256 / 64, KP / 64), 256>>>(KP, 256, KP, 2);
    taglin_kernel<<<dim3(KP, 2), 128>>>(1, Wgp, bgp);
    // pooled NCE
    gram_kernel<<<dim3(KP / 32, KP / 32), dim3(32, 32)>>>(2, KP);
    lse_kernel<<<KP, 256>>>(2);
    lse_kernel<<<KP, 256>>>(3);
    // total loss
    finalize_kernel<<<1, 1024>>>(out);
}

// round 5
// speedup vs baseline: 1.4342x; 1.4342x over previous
#include <cuda_runtime.h>
#include <cuda_bf16.h>
#include <math.h>

#define NN   2048      // num nodes
#define CD   512       // input channels
#define DD   128       // embed dim
#define KP   1024      // pooled nodes
#define NW   64        // bit words per row (2048/32)

// ---------------- scratch (device globals; branch-major [2][rows][128]) ----------------
__device__ float    g_FE [2 * NN * 128];   // slab0 teacher f_et, slab1 student f_es
__device__ float    g_A  [NN * NN];        // binary adjacency as f32
__device__ unsigned g_Abits[NN * NW];      // bit-packed adjacency rows
__device__ float    g_dinv[NN];
__device__ float    g_S  [2 * NN * 128];   // prescaled hop input (also pooled reuse)
__device__ float    g_H1 [2 * NN * 128];
__device__ float    g_H2 [2 * NN * 128];
__device__ float    g_FG [2 * NN * 128];   // f_gt | f_gs
__device__ float    g_TMP[2 * NN * 128];   // pre-norm GEMM output scratch
__device__ float    g_G  [NN * NN];        // NCE gram
__device__ float    g_Gp [KP * KP];        // pooled NCE gram
__device__ float    g_scores[NN];
__device__ int      g_idx [KP];
__device__ float    g_vals[KP];
__device__ float    g_NH [2 * KP * 128];   // new_ht | new_hs
__device__ float    g_Ap [KP * KP];
__device__ float    g_dinvp[KP];
__device__ float    g_Hp1[2 * KP * 128];
__device__ float    g_FP [2 * KP * 128];   // f_pt | f_ps
__device__ float    g_cgs[NN], g_cgt[NN], g_cps[KP], g_cpt[KP];

// ============================================================================
// Generic 64x64-tile NN GEMM, 256 threads, 4x4 micro-tile, k-step 16.
// mode 0 EMBED  : A=[ft;fs] (4096x512), B=W_embed(512x128), C=g_TMP (+bias)
// mode 1 HOP1   : A=g_A (2048x2048),    B=g_S branch-major, C=g_H1 * dinv
// mode 2 HOP2   : A=g_A,                B=g_S,              C=g_H2 * dinv
// mode 3 HOPP   : A=g_Ap(1024x1024),    B=g_S pooled,       C=g_Hp1 * dinvp
// mode 4 TAGLIN : A=[FE|H1|H2](4096x384), B=W_gnn(384x128), C=g_TMP (+bias)
// mode 5 TAGLINP: A=[NH|Hp1](2048x256),   B=W_gnnp(256x128),C=g_TMP (+bias)
// ============================================================================
__global__ void __launch_bounds__(256) gemm_nn(int mode, int K,
    const float* __restrict__ fs, const float* __restrict__ ft,
    const float* __restrict__ Wb, const float* __restrict__ bias) {
    __shared__ float As[16][64];   // k-major
    __shared__ float Bs[16][64];
    int tid = threadIdx.x;
    int tx = tid & 15, ty = tid >> 4;
    int bx = blockIdx.x, by = blockIdx.y;
    int n0 = bx * 64;
    int br = n0 >> 7, ncol = n0 & 127;   // for branch-major B / C (modes 1-3)
    int am = tid >> 2, akq = (tid & 3) << 2;
    int bk = tid >> 4, bnq = (tid & 15) << 2;
    int gmA = by * 64 + am;
    float acc[4][4] = {};
    const float* arow = nullptr;
    if (mode == 0) arow = (gmA < NN) ? ft + (size_t)gmA * CD : fs + (size_t)(gmA - NN) * CD;
    else if (mode == 1 || mode == 2) arow = g_A + (size_t)gmA * NN;
    else if (mode == 3) arow = g_Ap + (size_t)gmA * KP;

    for (int k0 = 0; k0 < K; k0 += 16) {
        int ka = k0 + akq;
        float4 av;
        if (mode == 4) {
            int part = ka >> 7;
            const float* p = (part == 0) ? g_FE : (part == 1 ? g_H1 : g_H2);
            av = *(const float4*)&p[(size_t)gmA * 128 + (ka & 127)];
        } else if (mode == 5) {
            int part = ka >> 7;
            const float* p = (part == 0) ? g_NH : g_Hp1;
            av = *(const float4*)&p[(size_t)gmA * 128 + (ka & 127)];
        } else {
            av = *(const float4*)&arow[ka];
        }
        int kb = k0 + bk;
        float4 bv;
        if (mode == 1 || mode == 2)
            bv = *(const float4*)&g_S[((size_t)br * NN + kb) * 128 + ncol + bnq];
        else if (mode == 3)
            bv = *(const float4*)&g_S[((size_t)br * KP + kb) * 128 + ncol + bnq];
        else
            bv = *(const float4*)&Wb[(size_t)kb * 128 + n0 + bnq];
        As[akq + 0][am] = av.x; As[akq + 1][am] = av.y;
        As[akq + 2][am] = av.z; As[akq + 3][am] = av.w;
        *(float4*)&Bs[bk][bnq] = bv;
        __syncthreads();
#pragma unroll
        for (int k = 0; k < 16; k++) {
            float4 a4 = *(float4*)&As[k][ty * 4];
            float4 b4 = *(float4*)&Bs[k][tx * 4];
            float a_[4] = { a4.x, a4.y, a4.z, a4.w };
            float b_[4] = { b4.x, b4.y, b4.z, b4.w };
#pragma unroll
            for (int i = 0; i < 4; i++)
#pragma unroll
                for (int j = 0; j < 4; j++) acc[i][j] = fmaf(a_[i], b_[j], acc[i][j]);
        }
        __syncthreads();
    }

    if (mode == 0 || mode == 4 || mode == 5) {
        int c0 = n0 + tx * 4;
        float b0 = bias[c0], b1 = bias[c0 + 1], b2 = bias[c0 + 2], b3 = bias[c0 + 3];
#pragma unroll
        for (int i = 0; i < 4; i++) {
            int r = by * 64 + ty * 4 + i;
            float4 v = make_float4(acc[i][0] + b0, acc[i][1] + b1, acc[i][2] + b2, acc[i][3] + b3);
            *(float4*)&g_TMP[(size_t)r * 128 + c0] = v;
        }
    } else {
        float* dst; const float* rs; int rowsz;
        if (mode == 1)      { dst = g_H1;  rs = g_dinv;  rowsz = NN; }
        else if (mode == 2) { dst = g_H2;  rs = g_dinv;  rowsz = NN; }
        else                { dst = g_Hp1; rs = g_dinvp; rowsz = KP; }
#pragma unroll
        for (int i = 0; i < 4; i++) {
            int r = by * 64 + ty * 4 + i;
            float rv = rs[r];
            float4 v = make_float4(acc[i][0] * rv, acc[i][1] * rv, acc[i][2] * rv, acc[i][3] * rv);
            *(float4*)&dst[((size_t)br * rowsz + r) * 128 + ncol + tx * 4] = v;
        }
    }
}

// ============================================================================
// NT gram: C = L @ R^T, L,R row-major [n,128]. 64x64 tiles, 4x4 micro.
// mode 0 ADJ: L=R=g_FE(teacher) -> g_A as 0/1  |  mode 1: f_gt.f_gs^T -> g_G
// mode 2: f_pt.f_ps^T -> g_Gp
// ============================================================================
__global__ void __launch_bounds__(256) gram_nt(int mode) {
    const float* L; const float* R; float* out; int n;
    if (mode == 0)      { L = g_FE; R = g_FE;            out = g_A;  n = NN; }
    else if (mode == 1) { L = g_FG; R = g_FG + NN * 128; out = g_G;  n = NN; }
    else                { L = g_FP; R = g_FP + KP * 128; out = g_Gp; n = KP; }
    __shared__ float Ls[16][64];
    __shared__ float Rs[16][64];
    int tid = threadIdx.x;
    int tx = tid & 15, ty = tid >> 4;
    int i0 = blockIdx.y * 64, j0 = blockIdx.x * 64;
    int lm = tid >> 2, lkq = (tid & 3) << 2;
    float acc[4][4] = {};
    for (int k0 = 0; k0 < 128; k0 += 16) {
        float4 a = *(const float4*)&L[(size_t)(i0 + lm) * 128 + k0 + lkq];
        float4 b = *(const float4*)&R[(size_t)(j0 + lm) * 128 + k0 + lkq];
        Ls[lkq + 0][lm] = a.x; Ls[lkq + 1][lm] = a.y; Ls[lkq + 2][lm] = a.z; Ls[lkq + 3][lm] = a.w;
        Rs[lkq + 0][lm] = b.x; Rs[lkq + 1][lm] = b.y; Rs[lkq + 2][lm] = b.z; Rs[lkq + 3][lm] = b.w;
        __syncthreads();
#pragma unroll
        for (int k = 0; k < 16; k++) {
            float4 a4 = *(float4*)&Ls[k][ty * 4];
            float4 b4 = *(float4*)&Rs[k][tx * 4];
            float a_[4] = { a4.x, a4.y, a4.z, a4.w };
            float b_[4] = { b4.x, b4.y, b4.z, b4.w };
#pragma unroll
            for (int i = 0; i < 4; i++)
#pragma unroll
                for (int j = 0; j < 4; j++) acc[i][j] = fmaf(a_[i], b_[j], acc[i][j]);
        }
        __syncthreads();
    }
#pragma unroll
    for (int i = 0; i < 4; i++) {
        int r = i0 + ty * 4 + i;
        float4 v;
        if (mode == 0)
            v = make_float4(acc[i][0] > 0.f ? 1.f : 0.f, acc[i][1] > 0.f ? 1.f : 0.f,
                            acc[i][2] > 0.f ? 1.f : 0.f, acc[i][3] > 0.f ? 1.f : 0.f);
        else
            v = make_float4(acc[i][0], acc[i][1], acc[i][2], acc[i][3]);
        *(float4*)&out[(size_t)r * n + j0 + tx * 4] = v;
    }
}

// ---------------- bit-pack adjacency rows ----------------
__global__ void abits_kernel() {
    int row = blockIdx.x;
    int warp = threadIdx.x >> 5, lane = threadIdx.x & 31;
    for (int w = warp; w < NW; w += 8) {
        float v = g_A[(size_t)row * NN + w * 32 + lane];
        unsigned b = __ballot_sync(0xffffffffu, v > 0.5f);
        if (lane == 0) g_Abits[row * NW + w] = b;
    }
}

// ---------------- degree + dinv from popcount ----------------
__global__ void deg_kernel() {
    int i = blockIdx.x * blockDim.x + threadIdx.x;
    if (i >= NN) return;
    unsigned s = 0;
#pragma unroll
    for (int w = 0; w < NW; w++) s += __popc(g_Abits[i * NW + w]);
    g_dinv[i] = rsqrtf((float)s);
}

// ---------------- row prescale into g_S (branch-major) ----------------
// mode 0: FE*dinv  1: H1*dinv  2: NH*dinvp
__global__ void scale_kernel(int mode) {
    int idx = blockIdx.x * blockDim.x + threadIdx.x;
    if (mode == 0)      g_S[idx] = g_FE[idx] * g_dinv[(idx >> 7) & (NN - 1)];
    else if (mode == 1) g_S[idx] = g_H1[idx] * g_dinv[(idx >> 7) & (NN - 1)];
    else                g_S[idx] = g_NH[idx] * g_dinvp[(idx >> 7) & (KP - 1)];
}

// ---------------- row l2-normalize from g_TMP, destination selected ON DEVICE ----------------
// (passing __device__ symbols as host-side kernel args is UB -> was the R3 bug)
// mode 0: -> g_FE   mode 1: -> g_FG   mode 2: -> g_FP
__global__ void rownorm_kernel(int mode) {
    float* dst = (mode == 0) ? g_FE : (mode == 1 ? g_FG : g_FP);
    int row = blockIdx.x, d = threadIdx.x;
    float v = g_TMP[(size_t)row * 128 + d];
    float s = v * v;
#pragma unroll
    for (int o = 16; o > 0; o >>= 1) s += __shfl_xor_sync(0xffffffffu, s, o);
    __shared__ float ws[4];
    if ((d & 31) == 0) ws[d >> 5] = s;
    __syncthreads();
    float tot = ws[0] + ws[1] + ws[2] + ws[3];
    dst[(size_t)row * 128 + d] = v * rsqrtf(tot);
}

// ---------------- NCE row/col LSE, single pass with fixed max M = 1/T ----------------
// all gram entries are dots of unit vectors -> g/T in [-1/T, 1/T]; -10/T filler
// underflows to exactly 0 in fp32 in the reference as well, so it is dropped.
__global__ void lse_kernel(int mode) {
    const float* G; float* contrib; int n; bool col;
    if (mode == 0)      { G = g_G;  contrib = g_cgs; n = NN; col = false; }
    else if (mode == 1) { G = g_G;  contrib = g_cgt; n = NN; col = true;  }
    else if (mode == 2) { G = g_Gp; contrib = g_cps; n = KP; col = false; }
    else                { G = g_Gp; contrib = g_cpt; n = KP; col = true;  }
    const float invT = 14.285714285714286f;   // 1/0.07
    int i = blockIdx.x, t = threadIdx.x;
    float pm = G[(size_t)i * n + i] * invT;
    __shared__ float red[256];
    float ls = 0.f;
    for (int j = t; j < n; j += 256) {
        if (j == i) continue;
        float g = col ? G[(size_t)j * n + i] : G[(size_t)i * n + j];
        ls += __expf(g * invT - invT);
    }
    red[t] = ls;
    __syncthreads();
    for (int s = 128; s > 0; s >>= 1) { if (t < s) red[t] += red[t + s]; __syncthreads(); }
    if (t == 0) {
        float S = red[0] + __expf(pm - invT);
        contrib[i] = invT + logf(S) - pm;
    }
}

// ---------------- pooling scores (teacher slab of g_FG) ----------------
__global__ void scores_kernel(const float* __restrict__ Wp, const float* __restrict__ bp) {
    int i = blockIdx.x * blockDim.x + threadIdx.x;
    if (i >= NN) return;
    float acc = bp[0];
#pragma unroll 8
    for (int d = 0; d < 128; d++) acc = fmaf(g_FG[(size_t)i * 128 + d], Wp[d], acc);
    g_scores[i] = 1.0f / (1.0f + __expf(-acc));
}

// ---------------- top-1024 of 2048 via one-block bitonic sort ----------------
__global__ void __launch_bounds__(1024) topk_kernel() {
    __shared__ float key[NN];
    __shared__ int   val[NN];
    int t = threadIdx.x;
    key[t]        = g_scores[t];        val[t]        = t;
    key[t + 1024] = g_scores[t + 1024]; val[t + 1024] = t + 1024;
    __syncthreads();
    for (int size = 2; size <= NN; size <<= 1) {
        for (int stride = size >> 1; stride > 0; stride >>= 1) {
            for (int half = 0; half < 2; half++) {
                int e = t + half * 1024;
                int j = e ^ stride;
                if (j > e) {
                    bool desc = ((e & size) == 0);
                    float ke = key[e], kj = key[j];
                    bool sw = desc ? (ke < kj) : (ke > kj);
                    if (sw) {
                        key[e] = kj; key[j] = ke;
                        int ve = val[e]; val[e] = val[j]; val[j] = ve;
                    }
                }
            }
            __syncthreads();
        }
    }
    if (t < KP) { g_idx[t] = val[t]; g_vals[t] = key[t]; }
}

// ---------------- gather + score-scale pooled features (branch-major) ----------------
__global__ void gather_kernel() {
    int a = blockIdx.x, br = blockIdx.y, c = threadIdx.x;
    g_NH[((size_t)br * KP + a) * 128 + c] =
        g_FG[((size_t)br * NN + g_idx[a]) * 128 + c] * g_vals[a];
}

// ---------------- pooled adjacency: Ap[a,b] = (bits[idx_a] & bits[idx_b]) != 0 ----------------
__global__ void ap_kernel() {
    __shared__ unsigned La[32][NW + 1];   // pad -> conflict-free Lb[tx][w]
    __shared__ unsigned Lb[32][NW + 1];
    int tx = threadIdx.x, ty = threadIdx.y;
    int tid = ty * 32 + tx;
    for (int e = tid; e < 32 * NW; e += 1024) {
        int r = e >> 6, w = e & 63;
        La[r][w] = g_Abits[(size_t)g_idx[blockIdx.y * 32 + r] * NW + w];
        Lb[r][w] = g_Abits[(size_t)g_idx[blockIdx.x * 32 + r] * NW + w];
    }
    __syncthreads();
    unsigned any = 0;
#pragma unroll
    for (int w = 0; w < NW; w++) any |= (La[ty][w] & Lb[tx][w]);
    g_Ap[(size_t)(blockIdx.y * 32 + ty) * KP + blockIdx.x * 32 + tx] = any ? 1.0f : 0.0f;
}

// ---------------- pooled degree ----------------
__global__ void degp_kernel() {
    int i = blockIdx.x, t = threadIdx.x;
    __shared__ float red[256];
    float s = 0.f;
    for (int j = t; j < KP; j += 256) s += g_Ap[(size_t)i * KP + j];
    red[t] = s;
    __syncthreads();
    for (int st = 128; st > 0; st >>= 1) { if (t < st) red[t] += red[t + st]; __syncthreads(); }
    if (t == 0) g_dinvp[i] = rsqrtf(red[0]);
}

// ---------------- final deterministic reduce ----------------
__global__ void __launch_bounds__(1024) finalize_kernel(float* out) {
    __shared__ float red[1024];
    int t = threadIdx.x;
    float v = (g_cgs[t] + g_cgs[t + 1024] + g_cgt[t] + g_cgt[t + 1024]) * (1.0f / 2048.0f)
            + (g_cps[t] + g_cpt[t]) * (1.0f / 1024.0f);
    red[t] = v;
    __syncthreads();
    for (int s = 512; s > 0; s >>= 1) { if (t < s) red[t] += red[t + s]; __syncthreads(); }
    if (t == 0) out[0] = red[0];
}

// ---------------- launch ----------------
extern "C" void kernel_launch(void* const* d_in, const int* in_sizes, int n_in,
                              void* d_out, int out_size) {
    const float* fs  = (const float*)d_in[0];
    const float* ft  = (const float*)d_in[1];
    const float* We  = (const float*)d_in[2];
    const float* be  = (const float*)d_in[3];
    const float* Wg  = (const float*)d_in[4];
    const float* bg  = (const float*)d_in[5];
    const float* Wp  = (const float*)d_in[6];
    const float* bp  = (const float*)d_in[7];
    const float* Wgp = (const float*)d_in[8];
    const float* bgp = (const float*)d_in[9];
    float* out = (float*)d_out;

    // embed both branches as one tiled GEMM (M=4096, N=128, K=512) + rownorm
    gemm_nn<<<dim3(2, 64), 256>>>(0, CD, fs, ft, We, be);
    rownorm_kernel<<<2 * NN, 128>>>(0);
    // adjacency from teacher features (float + bits + degree)
    gram_nt<<<dim3(NN / 64, NN / 64), 256>>>(0);
    abits_kernel<<<NN, 256>>>();
    deg_kernel<<<NN / 256, 256>>>();
    // hop 1 and hop 2 (teacher+student together, N=256)
    scale_kernel<<<(2 * NN * 128) / 256, 256>>>(0);
    gemm_nn<<<dim3(4, NN / 64), 256>>>(1, NN, fs, ft, nullptr, nullptr);
    scale_kernel<<<(2 * NN * 128) / 256, 256>>>(1);
    gemm_nn<<<dim3(4, NN / 64), 256>>>(2, NN, fs, ft, nullptr, nullptr);
    // TAGConv linear (K=384) + l2norm
    gemm_nn<<<dim3(2, 64), 256>>>(4, 384, fs, ft, Wg, bg);
    rownorm_kernel<<<2 * NN, 128>>>(1);
    // graph-level NCE
    gram_nt<<<dim3(NN / 64, NN / 64), 256>>>(1);
    lse_kernel<<<NN, 256>>>(0);
    lse_kernel<<<NN, 256>>>(1);
    // pooling
    scores_kernel<<<NN / 256, 256>>>(Wp, bp);
    topk_kernel<<<1, 1024>>>();
    gather_kernel<<<dim3(KP, 2), 128>>>();
    ap_kernel<<<dim3(KP / 32, KP / 32), dim3(32, 32)>>>();
    degp_kernel<<<KP, 256>>>();
    // pooled TAGConv (k=1)
    scale_kernel<<<(2 * KP * 128) / 256, 256>>>(2);
    gemm_nn<<<dim3(4, KP / 64), 256>>>(3, KP, fs, ft, nullptr, nullptr);
    gemm_nn<<<dim3(2, 32), 256>>>(5, 256, fs, ft, Wgp, bgp);
    rownorm_kernel<<<2 * KP, 128>>>(2);
    // pooled NCE
    gram_nt<<<dim3(KP / 64, KP / 64), 256>>>(2);
    lse_kernel<<<KP, 256>>>(2);
    lse_kernel<<<KP, 256>>>(3);
    // total loss
    finalize_kernel<<<1, 1024>>>(out);
}

// round 6
// speedup vs baseline: 1.9940x; 1.3903x over previous
#include <cuda_runtime.h>
#include <math.h>

#define NN 2048
#define CD 512
#define KP 1024
#define NW 64

// ---------------- device-global scratch ----------------
__device__ float    g_FE [2*NN*128];
__device__ float    g_A  [NN*NN];
__device__ unsigned g_Abits[NN*NW];
__device__ float    g_dinv[NN];
__device__ float    g_H1 [2*NN*128];
__device__ float    g_H2 [2*NN*128];
__device__ float    g_FG [2*NN*128];
__device__ float    g_TMP[2*NN*128];
__device__ float    g_G  [NN*NN];
__device__ float    g_Gp [KP*KP];
__device__ float    g_scores[NN];
__device__ int      g_idx[KP];
__device__ float    g_vals[KP];
__device__ float    g_NH [2*KP*128];
__device__ float    g_Ap [KP*KP];
__device__ float    g_dinvp[KP];
__device__ float    g_Hp1[2*KP*128];
__device__ float    g_FP [2*KP*128];
__device__ float    g_cgs[NN], g_cgt[NN], g_cps[KP], g_cpt[KP];

// ---------------- tf32 helpers ----------------
__device__ __forceinline__ unsigned f2tf(float x){
    unsigned u; asm("cvt.rna.tf32.f32 %0, %1;" : "=r"(u) : "f"(x)); return u;
}
__device__ __forceinline__ void mma8(float* c, const unsigned* a, const unsigned* b){
    asm volatile("mma.sync.aligned.m16n8k8.row.col.f32.tf32.tf32.f32 "
      "{%0,%1,%2,%3}, {%4,%5,%6,%7}, {%8,%9}, {%0,%1,%2,%3};"
      : "+f"(c[0]),"+f"(c[1]),"+f"(c[2]),"+f"(c[3])
      : "r"(a[0]),"r"(a[1]),"r"(a[2]),"r"(a[3]), "r"(b[0]),"r"(b[1]));
}

// ============================================================================
// tf32 NN GEMM: C[M,N] = A[M,K] @ B[K,N] (both row-major), 64x64 block tile,
// 128 threads = 4 warps (2x2), warp tile 32x32, k-chunk 64.
// mode 0 EMBED  : A=[ft;fs](4096x512), B=W_embed -> g_TMP (+bias)
// mode 1 HOP1   : A=g_A, B=g_FE * dinv[k] (staged) -> g_H1 * dinv[r]
// mode 2 HOP2   : A=g_A, B=g_H1 * dinv[k]          -> g_H2 * dinv[r]
// mode 3 HOPP   : A=g_Ap, B=g_NH * dinvp[k]        -> g_Hp1 * dinvp[r]
// mode 4 TAGLIN : A=[FE|H1|H2](4096x384), B=W_gnn  -> g_TMP (+bias)
// mode 5 TAGLINP: A=[NH|Hp1](2048x256),  B=W_gnnp  -> g_TMP (+bias)
// ============================================================================
__global__ void __launch_bounds__(128) mma_nn(int mode, int K,
    const float* __restrict__ fs, const float* __restrict__ ft,
    const float* __restrict__ Wb, const float* __restrict__ bias){
  __shared__ unsigned As[64*68];   // [m][k], stride 68 (mod32=4 -> conflict-free frags)
  __shared__ unsigned Bs[64*72];   // [k][n], stride 72 (mod32=8 -> conflict-free frags)
  int tid = threadIdx.x;
  int lane = tid & 31, wid = tid >> 5;
  int g = lane >> 2, t = lane & 3;
  int wm = (wid >> 1) * 32, wn = (wid & 1) * 32;
  int m0 = blockIdx.y * 64, n0 = blockIdx.x * 64;
  int br = n0 >> 7, ncol = n0 & 127;      // branch-major B/C for modes 1-3
  int srow = tid >> 1;                    // staging: 2 threads per row, 32 k each
  int sk   = (tid & 1) * 32;
  float c[2][4][4] = {};

  for (int k0 = 0; k0 < K; k0 += 64){
    // ---- stage A tile (64 rows x 64 k) ----
    {
      const float* ap;
      int r = m0 + srow;
      if (mode == 0)      ap = (r < NN) ? ft + (size_t)r*CD + k0 : fs + (size_t)(r-NN)*CD + k0;
      else if (mode == 1 || mode == 2) ap = g_A + (size_t)r*NN + k0;
      else if (mode == 3) ap = g_Ap + (size_t)r*KP + k0;
      else if (mode == 4){
        const float* buf = (k0 < 128) ? g_FE : (k0 < 256 ? g_H1 : g_H2);
        ap = buf + (size_t)r*128 + (k0 & 127);
      } else {
        const float* buf = (k0 < 128) ? g_NH : g_Hp1;
        ap = buf + (size_t)r*128 + (k0 & 127);
      }
#pragma unroll
      for (int j = 0; j < 8; j++){
        float4 v = *(const float4*)(ap + sk + 4*j);
        uint4 u = make_uint4(f2tf(v.x), f2tf(v.y), f2tf(v.z), f2tf(v.w));
        *(uint4*)&As[srow*68 + sk + 4*j] = u;
      }
    }
    // ---- stage B tile (64 k x 64 n), optional column scale dinv[k] ----
    {
      int kk = k0 + srow;
      const float* bp; float cs = 1.0f;
      if (mode == 1){      bp = g_FE + ((size_t)br*NN + kk)*128 + ncol; cs = g_dinv[kk]; }
      else if (mode == 2){ bp = g_H1 + ((size_t)br*NN + kk)*128 + ncol; cs = g_dinv[kk]; }
      else if (mode == 3){ bp = g_NH + ((size_t)br*KP + kk)*128 + ncol; cs = g_dinvp[kk]; }
      else                 bp = Wb + (size_t)kk*128 + n0;
#pragma unroll
      for (int j = 0; j < 8; j++){
        float4 v = *(const float4*)(bp + sk + 4*j);
        uint4 u = make_uint4(f2tf(v.x*cs), f2tf(v.y*cs), f2tf(v.z*cs), f2tf(v.w*cs));
        *(uint4*)&Bs[srow*72 + sk + 4*j] = u;
      }
    }
    __syncthreads();
#pragma unroll
    for (int k8 = 0; k8 < 64; k8 += 8){
      unsigned a[2][4], b[4][2];
#pragma unroll
      for (int mi = 0; mi < 2; mi++){
        int mb = wm + mi*16;
        a[mi][0] = As[(mb+g  )*68 + k8 + t];
        a[mi][1] = As[(mb+g+8)*68 + k8 + t];
        a[mi][2] = As[(mb+g  )*68 + k8 + t + 4];
        a[mi][3] = As[(mb+g+8)*68 + k8 + t + 4];
      }
#pragma unroll
      for (int ni = 0; ni < 4; ni++){
        int nb = wn + ni*8 + g;
        b[ni][0] = Bs[(k8+t  )*72 + nb];
        b[ni][1] = Bs[(k8+t+4)*72 + nb];
      }
#pragma unroll
      for (int mi = 0; mi < 2; mi++)
#pragma unroll
        for (int ni = 0; ni < 4; ni++) mma8(c[mi][ni], a[mi], b[ni]);
    }
    __syncthreads();
  }

  if (mode == 0 || mode == 4 || mode == 5){
#pragma unroll
    for (int mi = 0; mi < 2; mi++){
      int r0 = m0 + wm + mi*16 + g;
#pragma unroll
      for (int ni = 0; ni < 4; ni++){
        int col = n0 + wn + ni*8 + 2*t;
        float b0 = bias[col], b1 = bias[col+1];
        *(float2*)&g_TMP[(size_t)r0*128 + col]     = make_float2(c[mi][ni][0]+b0, c[mi][ni][1]+b1);
        *(float2*)&g_TMP[(size_t)(r0+8)*128 + col] = make_float2(c[mi][ni][2]+b0, c[mi][ni][3]+b1);
      }
    }
  } else {
    float* dst; const float* rs; int rows;
    if (mode == 1){      dst = g_H1;  rs = g_dinv;  rows = NN; }
    else if (mode == 2){ dst = g_H2;  rs = g_dinv;  rows = NN; }
    else {               dst = g_Hp1; rs = g_dinvp; rows = KP; }
#pragma unroll
    for (int mi = 0; mi < 2; mi++){
      int r0 = m0 + wm + mi*16 + g;
      float rv0 = rs[r0], rv1 = rs[r0+8];
#pragma unroll
      for (int ni = 0; ni < 4; ni++){
        int col = ncol + wn + ni*8 + 2*t;
        *(float2*)&dst[((size_t)br*rows + r0  )*128 + col] = make_float2(c[mi][ni][0]*rv0, c[mi][ni][1]*rv0);
        *(float2*)&dst[((size_t)br*rows + r0+8)*128 + col] = make_float2(c[mi][ni][2]*rv1, c[mi][ni][3]*rv1);
      }
    }
  }
}

// ============================================================================
// tf32 NT gram: C = L @ R^T, L,R row-major [n,128] (k contiguous = B col-major).
// mode 0: adjacency (g_FE teacher self-gram) -> g_A as 0/1
// mode 1: f_gt . f_gs^T -> g_G      mode 2: f_pt . f_ps^T -> g_Gp
// ============================================================================
__global__ void __launch_bounds__(128) mma_nt(int mode){
  const float* L; const float* R; float* out; int n;
  if (mode == 0){      L = g_FE; R = g_FE;                 out = g_A;  n = NN; }
  else if (mode == 1){ L = g_FG; R = g_FG + (size_t)NN*128; out = g_G;  n = NN; }
  else {               L = g_FP; R = g_FP + (size_t)KP*128; out = g_Gp; n = KP; }
  __shared__ unsigned Ls[64*68];
  __shared__ unsigned Rs[64*68];
  int tid = threadIdx.x;
  int lane = tid & 31, wid = tid >> 5;
  int g = lane >> 2, t = lane & 3;
  int wm = (wid >> 1) * 32, wn = (wid & 1) * 32;
  int i0 = blockIdx.y * 64, j0 = blockIdx.x * 64;
  int srow = tid >> 1, sk = (tid & 1) * 32;
  float c[2][4][4] = {};
  for (int k0 = 0; k0 < 128; k0 += 64){
    const float* lp = L + (size_t)(i0+srow)*128 + k0 + sk;
    const float* rp = R + (size_t)(j0+srow)*128 + k0 + sk;
#pragma unroll
    for (int j = 0; j < 8; j++){
      float4 v = *(const float4*)(lp + 4*j);
      *(uint4*)&Ls[srow*68 + sk + 4*j] = make_uint4(f2tf(v.x), f2tf(v.y), f2tf(v.z), f2tf(v.w));
      float4 w = *(const float4*)(rp + 4*j);
      *(uint4*)&Rs[srow*68 + sk + 4*j] = make_uint4(f2tf(w.x), f2tf(w.y), f2tf(w.z), f2tf(w.w));
    }
    __syncthreads();
#pragma unroll
    for (int k8 = 0; k8 < 64; k8 += 8){
      unsigned a[2][4], b[4][2];
#pragma unroll
      for (int mi = 0; mi < 2; mi++){
        int mb = wm + mi*16;
        a[mi][0] = Ls[(mb+g  )*68 + k8 + t];
        a[mi][1] = Ls[(mb+g+8)*68 + k8 + t];
        a[mi][2] = Ls[(mb+g  )*68 + k8 + t + 4];
        a[mi][3] = Ls[(mb+g+8)*68 + k8 + t + 4];
      }
#pragma unroll
      for (int ni = 0; ni < 4; ni++){
        int nb = wn + ni*8 + g;
        b[ni][0] = Rs[nb*68 + k8 + t];
        b[ni][1] = Rs[nb*68 + k8 + t + 4];
      }
#pragma unroll
      for (int mi = 0; mi < 2; mi++)
#pragma unroll
        for (int ni = 0; ni < 4; ni++) mma8(c[mi][ni], a[mi], b[ni]);
    }
    __syncthreads();
  }
#pragma unroll
  for (int mi = 0; mi < 2; mi++){
    int r0 = i0 + wm + mi*16 + g;
#pragma unroll
    for (int ni = 0; ni < 4; ni++){
      int col = j0 + wn + ni*8 + 2*t;
      float v0 = c[mi][ni][0], v1 = c[mi][ni][1], v2 = c[mi][ni][2], v3 = c[mi][ni][3];
      if (mode == 0){
        v0 = v0 > 0.f ? 1.f : 0.f; v1 = v1 > 0.f ? 1.f : 0.f;
        v2 = v2 > 0.f ? 1.f : 0.f; v3 = v3 > 0.f ? 1.f : 0.f;
      }
      *(float2*)&out[(size_t)r0*n + col]     = make_float2(v0, v1);
      *(float2*)&out[(size_t)(r0+8)*n + col] = make_float2(v2, v3);
    }
  }
}

// ---------------- bit-pack adjacency rows ----------------
__global__ void abits_kernel() {
    int row = blockIdx.x;
    int warp = threadIdx.x >> 5, lane = threadIdx.x & 31;
    for (int w = warp; w < NW; w += 8) {
        float v = g_A[(size_t)row * NN + w * 32 + lane];
        unsigned b = __ballot_sync(0xffffffffu, v > 0.5f);
        if (lane == 0) g_Abits[row * NW + w] = b;
    }
}

// ---------------- degree + dinv from popcount ----------------
__global__ void deg_kernel() {
    int i = blockIdx.x * blockDim.x + threadIdx.x;
    if (i >= NN) return;
    unsigned s = 0;
#pragma unroll
    for (int w = 0; w < NW; w++) s += __popc(g_Abits[i * NW + w]);
    g_dinv[i] = rsqrtf((float)s);
}

// ---------------- row l2-normalize from g_TMP; dst selected on device ----------------
__global__ void rownorm_kernel(int mode) {
    float* dst = (mode == 0) ? g_FE : (mode == 1 ? g_FG : g_FP);
    int row = blockIdx.x, d = threadIdx.x;
    float v = g_TMP[(size_t)row * 128 + d];
    float s = v * v;
#pragma unroll
    for (int o = 16; o > 0; o >>= 1) s += __shfl_xor_sync(0xffffffffu, s, o);
    __shared__ float ws[4];
    if ((d & 31) == 0) ws[d >> 5] = s;
    __syncthreads();
    float tot = ws[0] + ws[1] + ws[2] + ws[3];
    dst[(size_t)row * 128 + d] = v * rsqrtf(tot);
}

// ---------------- NCE row/col LSE, single pass, fixed max M = 1/T ----------------
__global__ void lse_kernel(int mode) {
    const float* G; float* contrib; int n; bool col;
    if (mode == 0)      { G = g_G;  contrib = g_cgs; n = NN; col = false; }
    else if (mode == 1) { G = g_G;  contrib = g_cgt; n = NN; col = true;  }
    else if (mode == 2) { G = g_Gp; contrib = g_cps; n = KP; col = false; }
    else                { G = g_Gp; contrib = g_cpt; n = KP; col = true;  }
    const float invT = 14.285714285714286f;
    int i = blockIdx.x, t = threadIdx.x;
    float pm = G[(size_t)i * n + i] * invT;
    __shared__ float red[256];
    float ls = 0.f;
    for (int j = t; j < n; j += 256) {
        if (j == i) continue;
        float g = col ? G[(size_t)j * n + i] : G[(size_t)i * n + j];
        ls += __expf(g * invT - invT);
    }
    red[t] = ls;
    __syncthreads();
    for (int s = 128; s > 0; s >>= 1) { if (t < s) red[t] += red[t + s]; __syncthreads(); }
    if (t == 0) {
        float S = red[0] + __expf(pm - invT);
        contrib[i] = invT + logf(S) - pm;
    }
}

// ---------------- pooling scores ----------------
__global__ void scores_kernel(const float* __restrict__ Wp, const float* __restrict__ bp) {
    int i = blockIdx.x * blockDim.x + threadIdx.x;
    if (i >= NN) return;
    float acc = bp[0];
#pragma unroll 8
    for (int d = 0; d < 128; d++) acc = fmaf(g_FG[(size_t)i * 128 + d], Wp[d], acc);
    g_scores[i] = 1.0f / (1.0f + __expf(-acc));
}

// ---------------- top-1024 of 2048 via one-block bitonic sort ----------------
__global__ void __launch_bounds__(1024) topk_kernel() {
    __shared__ float key[NN];
    __shared__ int   val[NN];
    int t = threadIdx.x;
    key[t]        = g_scores[t];        val[t]        = t;
    key[t + 1024] = g_scores[t + 1024]; val[t + 1024] = t + 1024;
    __syncthreads();
    for (int size = 2; size <= NN; size <<= 1) {
        for (int stride = size >> 1; stride > 0; stride >>= 1) {
            for (int half = 0; half < 2; half++) {
                int e = t + half * 1024;
                int j = e ^ stride;
                if (j > e) {
                    bool desc = ((e & size) == 0);
                    float ke = key[e], kj = key[j];
                    bool sw = desc ? (ke < kj) : (ke > kj);
                    if (sw) {
                        key[e] = kj; key[j] = ke;
                        int ve = val[e]; val[e] = val[j]; val[j] = ve;
                    }
                }
            }
            __syncthreads();
        }
    }
    if (t < KP) { g_idx[t] = val[t]; g_vals[t] = key[t]; }
}

// ---------------- gather + score-scale pooled features ----------------
__global__ void gather_kernel() {
    int a = blockIdx.x, br = blockIdx.y, c = threadIdx.x;
    g_NH[((size_t)br * KP + a) * 128 + c] =
        g_FG[((size_t)br * NN + g_idx[a]) * 128 + c] * g_vals[a];
}

// ---------------- pooled adjacency via bitmask AND ----------------
__global__ void ap_kernel() {
    __shared__ unsigned La[32][NW + 1];
    __shared__ unsigned Lb[32][NW + 1];
    int tx = threadIdx.x, ty = threadIdx.y;
    int tid = ty * 32 + tx;
    for (int e = tid; e < 32 * NW; e += 1024) {
        int r = e >> 6, w = e & 63;
        La[r][w] = g_Abits[(size_t)g_idx[blockIdx.y * 32 + r] * NW + w];
        Lb[r][w] = g_Abits[(size_t)g_idx[blockIdx.x * 32 + r] * NW + w];
    }
    __syncthreads();
    unsigned any = 0;
#pragma unroll
    for (int w = 0; w < NW; w++) any |= (La[ty][w] & Lb[tx][w]);
    g_Ap[(size_t)(blockIdx.y * 32 + ty) * KP + blockIdx.x * 32 + tx] = any ? 1.0f : 0.0f;
}

// ---------------- pooled degree ----------------
__global__ void degp_kernel() {
    int i = blockIdx.x, t = threadIdx.x;
    __shared__ float red[256];
    float s = 0.f;
    for (int j = t; j < KP; j += 256) s += g_Ap[(size_t)i * KP + j];
    red[t] = s;
    __syncthreads();
    for (int st = 128; st > 0; st >>= 1) { if (t < st) red[t] += red[t + st]; __syncthreads(); }
    if (t == 0) g_dinvp[i] = rsqrtf(red[0]);
}

// ---------------- final deterministic reduce ----------------
__global__ void __launch_bounds__(1024) finalize_kernel(float* out) {
    __shared__ float red[1024];
    int t = threadIdx.x;
    float v = (g_cgs[t] + g_cgs[t + 1024] + g_cgt[t] + g_cgt[t + 1024]) * (1.0f / 2048.0f)
            + (g_cps[t] + g_cpt[t]) * (1.0f / 1024.0f);
    red[t] = v;
    __syncthreads();
    for (int s = 512; s > 0; s >>= 1) { if (t < s) red[t] += red[t + s]; __syncthreads(); }
    if (t == 0) out[0] = red[0];
}

// ---------------- launch ----------------
extern "C" void kernel_launch(void* const* d_in, const int* in_sizes, int n_in,
                              void* d_out, int out_size) {
    const float* fs  = (const float*)d_in[0];
    const float* ft  = (const float*)d_in[1];
    const float* We  = (const float*)d_in[2];
    const float* be  = (const float*)d_in[3];
    const float* Wg  = (const float*)d_in[4];
    const float* bg  = (const float*)d_in[5];
    const float* Wp  = (const float*)d_in[6];
    const float* bp  = (const float*)d_in[7];
    const float* Wgp = (const float*)d_in[8];
    const float* bgp = (const float*)d_in[9];
    float* out = (float*)d_out;

    // embed both branches (M=4096, N=128, K=512) + rownorm
    mma_nn<<<dim3(2, 64), 128>>>(0, CD, fs, ft, We, be);
    rownorm_kernel<<<2 * NN, 128>>>(0);
    // adjacency (float + bits + degree)
    mma_nt<<<dim3(NN / 64, NN / 64), 128>>>(0);
    abits_kernel<<<NN, 256>>>();
    deg_kernel<<<NN / 256, 256>>>();
    // hop1, hop2 (dinv[k] fused into B staging; dinv[r] in epilogue)
    mma_nn<<<dim3(4, NN / 64), 128>>>(1, NN, fs, ft, nullptr, nullptr);
    mma_nn<<<dim3(4, NN / 64), 128>>>(2, NN, fs, ft, nullptr, nullptr);
    // TAGConv linear (K=384) + l2norm
    mma_nn<<<dim3(2, 64), 128>>>(4, 384, fs, ft, Wg, bg);
    rownorm_kernel<<<2 * NN, 128>>>(1);
    // graph-level NCE
    mma_nt<<<dim3(NN / 64, NN / 64), 128>>>(1);
    lse_kernel<<<NN, 256>>>(0);
    lse_kernel<<<NN, 256>>>(1);
    // pooling
    scores_kernel<<<NN / 256, 256>>>(Wp, bp);
    topk_kernel<<<1, 1024>>>();
    gather_kernel<<<dim3(KP, 2), 128>>>();
    ap_kernel<<<dim3(KP / 32, KP / 32), dim3(32, 32)>>>();
    degp_kernel<<<KP, 256>>>();
    // pooled TAGConv (k=1)
    mma_nn<<<dim3(4, KP / 64), 128>>>(3, KP, fs, ft, nullptr, nullptr);
    mma_nn<<<dim3(2, 32), 128>>>(5, 256, fs, ft, Wgp, bgp);
    rownorm_kernel<<<2 * KP, 128>>>(2);
    // pooled NCE
    mma_nt<<<dim3(KP / 64, KP / 64), 128>>>(2);
    lse_kernel<<<KP, 256>>>(2);
    lse_kernel<<<KP, 256>>>(3);
    // total loss
    finalize_kernel<<<1, 1024>>>(out);
}

// round 7
// speedup vs baseline: 2.2039x; 1.1052x over previous
#include <cuda_runtime.h>
#include <math.h>

#define NN 2048
#define CD 512
#define KP 1024
#define NW 64

// ---------------- device-global scratch ----------------
__device__ float    g_FE [2*NN*128];
__device__ unsigned g_Abits[NN*NW];
__device__ float    g_dinv[NN];
__device__ float    g_H1 [2*NN*128];
__device__ float    g_H2 [2*NN*128];
__device__ float    g_FG [2*NN*128];
__device__ float    g_TMP[2*NN*128];
__device__ float    g_G  [NN*NN];
__device__ float    g_Gp [KP*KP];
__device__ float    g_rp [NN*32];        // LSE row partials (per 64-col tile)
__device__ float    g_cp [NN*32];        // LSE col partials (per 64-row tile)
__device__ float    g_scores[NN];
__device__ int      g_idx[KP];
__device__ float    g_vals[KP];
__device__ float    g_NH [2*KP*128];
__device__ float    g_Ap [KP*KP];
__device__ float    g_dinvp[KP];
__device__ float    g_Hp1[2*KP*128];
__device__ float    g_FP [2*KP*128];
__device__ float    g_cgs[NN], g_cgt[NN], g_cps[KP], g_cpt[KP];

// ---------------- tf32 helpers ----------------
__device__ __forceinline__ unsigned f2tf(float x){
    unsigned u; asm("cvt.rna.tf32.f32 %0, %1;" : "=r"(u) : "f"(x)); return u;
}
__device__ __forceinline__ void mma8(float* c, const unsigned* a, const unsigned* b){
    asm volatile("mma.sync.aligned.m16n8k8.row.col.f32.tf32.tf32.f32 "
      "{%0,%1,%2,%3}, {%4,%5,%6,%7}, {%8,%9}, {%0,%1,%2,%3};"
      : "+f"(c[0]),"+f"(c[1]),"+f"(c[2]),"+f"(c[3])
      : "r"(a[0]),"r"(a[1]),"r"(a[2]),"r"(a[3]), "r"(b[0]),"r"(b[1]));
}

// ============================================================================
// tf32 NN GEMM, 64x64 tile, 4 warps (2x2), warp tile 32x32, k-chunk 64.
// mode 0 EMBED  : A=[ft;fs](4096x512), B=W_embed -> g_TMP (+bias)
// mode 1 HOP1   : A=bits(g_Abits),  B=g_FE * dinv[k] -> g_H1 * dinv[r]
// mode 2 HOP2   : A=bits(g_Abits),  B=g_H1 * dinv[k] -> g_H2 * dinv[r]
// mode 3 HOPP   : A=g_Ap (float),   B=g_NH * dinvp[k] -> g_Hp1 * dinvp[r]
// mode 4 TAGLIN : A=[FE|H1|H2](4096x384), B=W_gnn  -> g_TMP (+bias)
// mode 5 TAGLINP: A=[NH|Hp1](2048x256),  B=W_gnnp  -> g_TMP (+bias)
// ============================================================================
__global__ void __launch_bounds__(128) mma_nn(int mode, int K,
    const float* __restrict__ fs, const float* __restrict__ ft,
    const float* __restrict__ Wb, const float* __restrict__ bias){
  __shared__ unsigned As[64*68];
  __shared__ unsigned Bs[64*72];
  int tid = threadIdx.x;
  int lane = tid & 31, wid = tid >> 5;
  int g = lane >> 2, t = lane & 3;
  int wm = (wid >> 1) * 32, wn = (wid & 1) * 32;
  int m0 = blockIdx.y * 64, n0 = blockIdx.x * 64;
  int br = n0 >> 7, ncol = n0 & 127;
  int srow = tid >> 1;
  int sk   = (tid & 1) * 32;
  float c[2][4][4] = {};

  for (int k0 = 0; k0 < K; k0 += 64){
    // ---- stage A tile ----
    {
      int r = m0 + srow;
      if (mode == 1 || mode == 2){
        unsigned w = g_Abits[(size_t)r*NW + ((k0 + sk) >> 5)];
#pragma unroll
        for (int j = 0; j < 8; j++){
          uint4 u;
          u.x = (w >> (4*j+0)) & 1 ? 0x3F800000u : 0u;
          u.y = (w >> (4*j+1)) & 1 ? 0x3F800000u : 0u;
          u.z = (w >> (4*j+2)) & 1 ? 0x3F800000u : 0u;
          u.w = (w >> (4*j+3)) & 1 ? 0x3F800000u : 0u;
          *(uint4*)&As[srow*68 + sk + 4*j] = u;
        }
      } else {
        const float* ap;
        if (mode == 0)      ap = (r < NN) ? ft + (size_t)r*CD + k0 : fs + (size_t)(r-NN)*CD + k0;
        else if (mode == 3) ap = g_Ap + (size_t)r*KP + k0;
        else if (mode == 4){
          const float* buf = (k0 < 128) ? g_FE : (k0 < 256 ? g_H1 : g_H2);
          ap = buf + (size_t)r*128 + (k0 & 127);
        } else {
          const float* buf = (k0 < 128) ? g_NH : g_Hp1;
          ap = buf + (size_t)r*128 + (k0 & 127);
        }
#pragma unroll
        for (int j = 0; j < 8; j++){
          float4 v = *(const float4*)(ap + sk + 4*j);
          *(uint4*)&As[srow*68 + sk + 4*j] = make_uint4(f2tf(v.x), f2tf(v.y), f2tf(v.z), f2tf(v.w));
        }
      }
    }
    // ---- stage B tile (optional column scale dinv[k]) ----
    {
      int kk = k0 + srow;
      const float* bp; float cs = 1.0f;
      if (mode == 1){      bp = g_FE + ((size_t)br*NN + kk)*128 + ncol; cs = g_dinv[kk]; }
      else if (mode == 2){ bp = g_H1 + ((size_t)br*NN + kk)*128 + ncol; cs = g_dinv[kk]; }
      else if (mode == 3){ bp = g_NH + ((size_t)br*KP + kk)*128 + ncol; cs = g_dinvp[kk]; }
      else                 bp = Wb + (size_t)kk*128 + n0;
#pragma unroll
      for (int j = 0; j < 8; j++){
        float4 v = *(const float4*)(bp + sk + 4*j);
        *(uint4*)&Bs[srow*72 + sk + 4*j] = make_uint4(f2tf(v.x*cs), f2tf(v.y*cs), f2tf(v.z*cs), f2tf(v.w*cs));
      }
    }
    __syncthreads();
#pragma unroll
    for (int k8 = 0; k8 < 64; k8 += 8){
      unsigned a[2][4], b[4][2];
#pragma unroll
      for (int mi = 0; mi < 2; mi++){
        int mb = wm + mi*16;
        a[mi][0] = As[(mb+g  )*68 + k8 + t];
        a[mi][1] = As[(mb+g+8)*68 + k8 + t];
        a[mi][2] = As[(mb+g  )*68 + k8 + t + 4];
        a[mi][3] = As[(mb+g+8)*68 + k8 + t + 4];
      }
#pragma unroll
      for (int ni = 0; ni < 4; ni++){
        int nb = wn + ni*8 + g;
        b[ni][0] = Bs[(k8+t  )*72 + nb];
        b[ni][1] = Bs[(k8+t+4)*72 + nb];
      }
#pragma unroll
      for (int mi = 0; mi < 2; mi++)
#pragma unroll
        for (int ni = 0; ni < 4; ni++) mma8(c[mi][ni], a[mi], b[ni]);
    }
    __syncthreads();
  }

  if (mode == 0 || mode == 4 || mode == 5){
#pragma unroll
    for (int mi = 0; mi < 2; mi++){
      int r0 = m0 + wm + mi*16 + g;
#pragma unroll
      for (int ni = 0; ni < 4; ni++){
        int col = n0 + wn + ni*8 + 2*t;
        float b0 = bias[col], b1 = bias[col+1];
        *(float2*)&g_TMP[(size_t)r0*128 + col]     = make_float2(c[mi][ni][0]+b0, c[mi][ni][1]+b1);
        *(float2*)&g_TMP[(size_t)(r0+8)*128 + col] = make_float2(c[mi][ni][2]+b0, c[mi][ni][3]+b1);
      }
    }
  } else {
    float* dst; const float* rs; int rows;
    if (mode == 1){      dst = g_H1;  rs = g_dinv;  rows = NN; }
    else if (mode == 2){ dst = g_H2;  rs = g_dinv;  rows = NN; }
    else {               dst = g_Hp1; rs = g_dinvp; rows = KP; }
#pragma unroll
    for (int mi = 0; mi < 2; mi++){
      int r0 = m0 + wm + mi*16 + g;
      float rv0 = rs[r0], rv1 = rs[r0+8];
#pragma unroll
      for (int ni = 0; ni < 4; ni++){
        int col = ncol + wn + ni*8 + 2*t;
        *(float2*)&dst[((size_t)br*rows + r0  )*128 + col] = make_float2(c[mi][ni][0]*rv0, c[mi][ni][1]*rv0);
        *(float2*)&dst[((size_t)br*rows + r0+8)*128 + col] = make_float2(c[mi][ni][2]*rv1, c[mi][ni][3]*rv1);
      }
    }
  }
}

// ============================================================================
// tf32 NT gram: C = L @ R^T.
// mode 0: adjacency (teacher self-gram) -> g_Abits DIRECTLY (smem atomicOr)
// mode 1: f_gt . f_gs^T -> g_G      mode 2: f_pt . f_ps^T -> g_Gp
// ============================================================================
__global__ void __launch_bounds__(128) mma_nt(int mode){
  const float* L; const float* R; float* out; int n;
  if (mode == 0){      L = g_FE; R = g_FE;                  out = nullptr; n = NN; }
  else if (mode == 1){ L = g_FG; R = g_FG + (size_t)NN*128; out = g_G;  n = NN; }
  else {               L = g_FP; R = g_FP + (size_t)KP*128; out = g_Gp; n = KP; }
  __shared__ unsigned Ls[64*68];
  __shared__ unsigned Rs[64*68];
  __shared__ unsigned bw[64*2];
  int tid = threadIdx.x;
  int lane = tid & 31, wid = tid >> 5;
  int g = lane >> 2, t = lane & 3;
  int wm = (wid >> 1) * 32, wn = (wid & 1) * 32;
  int i0 = blockIdx.y * 64, j0 = blockIdx.x * 64;
  int srow = tid >> 1, sk = (tid & 1) * 32;
  float c[2][4][4] = {};
  for (int k0 = 0; k0 < 128; k0 += 64){
    const float* lp = L + (size_t)(i0+srow)*128 + k0 + sk;
    const float* rp = R + (size_t)(j0+srow)*128 + k0 + sk;
#pragma unroll
    for (int j = 0; j < 8; j++){
      float4 v = *(const float4*)(lp + 4*j);
      *(uint4*)&Ls[srow*68 + sk + 4*j] = make_uint4(f2tf(v.x), f2tf(v.y), f2tf(v.z), f2tf(v.w));
      float4 w = *(const float4*)(rp + 4*j);
      *(uint4*)&Rs[srow*68 + sk + 4*j] = make_uint4(f2tf(w.x), f2tf(w.y), f2tf(w.z), f2tf(w.w));
    }
    __syncthreads();
#pragma unroll
    for (int k8 = 0; k8 < 64; k8 += 8){
      unsigned a[2][4], b[4][2];
#pragma unroll
      for (int mi = 0; mi < 2; mi++){
        int mb = wm + mi*16;
        a[mi][0] = Ls[(mb+g  )*68 + k8 + t];
        a[mi][1] = Ls[(mb+g+8)*68 + k8 + t];
        a[mi][2] = Ls[(mb+g  )*68 + k8 + t + 4];
        a[mi][3] = Ls[(mb+g+8)*68 + k8 + t + 4];
      }
#pragma unroll
      for (int ni = 0; ni < 4; ni++){
        int nb = wn + ni*8 + g;
        b[ni][0] = Rs[nb*68 + k8 + t];
        b[ni][1] = Rs[nb*68 + k8 + t + 4];
      }
#pragma unroll
      for (int mi = 0; mi < 2; mi++)
#pragma unroll
        for (int ni = 0; ni < 4; ni++) mma8(c[mi][ni], a[mi], b[ni]);
    }
    __syncthreads();
  }
  if (mode == 0){
    // accumulate sign bits into 2 words per local row (order-independent OR)
    if (tid < 128) bw[tid] = 0;
    __syncthreads();
#pragma unroll
    for (int mi = 0; mi < 2; mi++){
      int lr = wm + mi*16 + g;
#pragma unroll
      for (int ni = 0; ni < 4; ni++){
        int lc = wn + ni*8 + 2*t;
        unsigned m0w = (c[mi][ni][0] > 0.f ? 1u << (lc & 31) : 0u)
                     | (c[mi][ni][1] > 0.f ? 2u << (lc & 31) : 0u);
        if (m0w) atomicOr(&bw[lr*2 + (lc >> 5)], m0w);
        unsigned m1w = (c[mi][ni][2] > 0.f ? 1u << (lc & 31) : 0u)
                     | (c[mi][ni][3] > 0.f ? 2u << (lc & 31) : 0u);
        if (m1w) atomicOr(&bw[(lr+8)*2 + (lc >> 5)], m1w);
      }
    }
    __syncthreads();
    if (tid < 128)
      g_Abits[(size_t)(i0 + (tid >> 1))*NW + (j0 >> 5) + (tid & 1)] = bw[tid];
  } else {
#pragma unroll
    for (int mi = 0; mi < 2; mi++){
      int r0 = i0 + wm + mi*16 + g;
#pragma unroll
      for (int ni = 0; ni < 4; ni++){
        int col = j0 + wn + ni*8 + 2*t;
        *(float2*)&out[(size_t)r0*n + col]     = make_float2(c[mi][ni][0], c[mi][ni][1]);
        *(float2*)&out[(size_t)(r0+8)*n + col] = make_float2(c[mi][ni][2], c[mi][ni][3]);
      }
    }
  }
}

// ---------------- degree + dinv from popcount ----------------
__global__ void deg_kernel() {
    int i = blockIdx.x * blockDim.x + threadIdx.x;
    if (i >= NN) return;
    unsigned s = 0;
#pragma unroll
    for (int w = 0; w < NW; w++) s += __popc(g_Abits[i * NW + w]);
    g_dinv[i] = rsqrtf((float)s);
}

// ---------------- row l2-normalize from g_TMP; dst selected on device ----------------
__global__ void rownorm_kernel(int mode) {
    float* dst = (mode == 0) ? g_FE : (mode == 1 ? g_FG : g_FP);
    int row = blockIdx.x, d = threadIdx.x;
    float v = g_TMP[(size_t)row * 128 + d];
    float s = v * v;
#pragma unroll
    for (int o = 16; o > 0; o >>= 1) s += __shfl_xor_sync(0xffffffffu, s, o);
    __shared__ float ws[4];
    if ((d & 31) == 0) ws[d >> 5] = s;
    __syncthreads();
    float tot = ws[0] + ws[1] + ws[2] + ws[3];
    dst[(size_t)row * 128 + d] = v * rsqrtf(tot);
}

// ============================================================================
// Fused LSE pass 1: 64x64 tiles of G (or Gp); exp computed once per element,
// per-tile row partials -> g_rp[row*nt + bx], col partials -> g_cp[col*nt + by].
// mode 0: g_G (n=2048, nt=32)   mode 1: g_Gp (n=1024, nt=16)
// ============================================================================
__global__ void __launch_bounds__(256) lse_tile(int mode){
  const float* G; int n, nt;
  if (mode == 0){ G = g_G;  n = NN; nt = 32; }
  else          { G = g_Gp; n = KP; nt = 16; }
  const float invT = 14.285714285714286f;
  __shared__ float es[64*65];
  int tid = threadIdx.x;
  int i0 = blockIdx.y * 64, j0 = blockIdx.x * 64;
  // load + exp (diag excluded)
  for (int e = tid; e < 4096; e += 256){
    int r = e >> 6, c = e & 63;
    float gv = G[(size_t)(i0+r)*n + j0 + c];
    float ev = (i0 + r == j0 + c) ? 0.f : __expf(gv*invT - invT);
    es[r*65 + c] = ev;
  }
  __syncthreads();
  int lane = tid & 31, w = tid >> 5;     // 8 warps
  // row partials: warp w owns rows 8w..8w+7
#pragma unroll
  for (int rr = 0; rr < 8; rr++){
    int r = w*8 + rr;
    float s = es[r*65 + lane] + es[r*65 + lane + 32];
#pragma unroll
    for (int o = 16; o > 0; o >>= 1) s += __shfl_xor_sync(0xffffffffu, s, o);
    if (lane == 0) g_rp[(size_t)(i0 + r)*nt + blockIdx.x] = s;
  }
  // col partials: warp w owns cols 8w..8w+7
#pragma unroll
  for (int cc = 0; cc < 8; cc++){
    int c = w*8 + cc;
    float s = es[lane*65 + c] + es[(lane+32)*65 + c];
#pragma unroll
    for (int o = 16; o > 0; o >>= 1) s += __shfl_xor_sync(0xffffffffu, s, o);
    if (lane == 0) g_cp[(size_t)(j0 + c)*nt + blockIdx.y] = s;
  }
}

// LSE pass 2: fixed-order partial reduce + contribution for row AND col sides.
// mode 0: -> g_cgs/g_cgt (diag from g_G)   mode 1: -> g_cps/g_cpt (g_Gp)
__global__ void lse_final(int mode){
  const float* G; int n, nt; float *cr, *cc;
  if (mode == 0){ G = g_G;  n = NN; nt = 32; cr = g_cgs; cc = g_cgt; }
  else          { G = g_Gp; n = KP; nt = 16; cr = g_cps; cc = g_cpt; }
  const float invT = 14.285714285714286f;
  int i = blockIdx.x * blockDim.x + threadIdx.x;
  if (i >= n) return;
  float pm = G[(size_t)i*n + i] * invT;
  float pe = __expf(pm - invT);
  float sr = 0.f, sc = 0.f;
  for (int k = 0; k < nt; k++){ sr += g_rp[(size_t)i*nt + k]; sc += g_cp[(size_t)i*nt + k]; }
  cr[i] = invT + logf(sr + pe) - pm;
  cc[i] = invT + logf(sc + pe) - pm;
}

// ---------------- pooling scores ----------------
__global__ void scores_kernel(const float* __restrict__ Wp, const float* __restrict__ bp) {
    int i = blockIdx.x * blockDim.x + threadIdx.x;
    if (i >= NN) return;
    float acc = bp[0];
#pragma unroll 8
    for (int d = 0; d < 128; d++) acc = fmaf(g_FG[(size_t)i * 128 + d], Wp[d], acc);
    g_scores[i] = 1.0f / (1.0f + __expf(-acc));
}

// ---------------- top-1024 of 2048 via one-block bitonic sort ----------------
__global__ void __launch_bounds__(1024) topk_kernel() {
    __shared__ float key[NN];
    __shared__ int   val[NN];
    int t = threadIdx.x;
    key[t]        = g_scores[t];        val[t]        = t;
    key[t + 1024] = g_scores[t + 1024]; val[t + 1024] = t + 1024;
    __syncthreads();
    for (int size = 2; size <= NN; size <<= 1) {
        for (int stride = size >> 1; stride > 0; stride >>= 1) {
            for (int half = 0; half < 2; half++) {
                int e = t + half * 1024;
                int j = e ^ stride;
                if (j > e) {
                    bool desc = ((e & size) == 0);
                    float ke = key[e], kj = key[j];
                    bool sw = desc ? (ke < kj) : (ke > kj);
                    if (sw) {
                        key[e] = kj; key[j] = ke;
                        int ve = val[e]; val[e] = val[j]; val[j] = ve;
                    }
                }
            }
            __syncthreads();
        }
    }
    if (t < KP) { g_idx[t] = val[t]; g_vals[t] = key[t]; }
}

// ---------------- gather + score-scale pooled features ----------------
__global__ void gather_kernel() {
    int a = blockIdx.x, br = blockIdx.y, c = threadIdx.x;
    g_NH[((size_t)br * KP + a) * 128 + c] =
        g_FG[((size_t)br * NN + g_idx[a]) * 128 + c] * g_vals[a];
}

// ---------------- pooled adjacency via bitmask AND ----------------
__global__ void ap_kernel() {
    __shared__ unsigned La[32][NW + 1];
    __shared__ unsigned Lb[32][NW + 1];
    int tx = threadIdx.x, ty = threadIdx.y;
    int tid = ty * 32 + tx;
    for (int e = tid; e < 32 * NW; e += 1024) {
        int r = e >> 6, w = e & 63;
        La[r][w] = g_Abits[(size_t)g_idx[blockIdx.y * 32 + r] * NW + w];
        Lb[r][w] = g_Abits[(size_t)g_idx[blockIdx.x * 32 + r] * NW + w];
    }
    __syncthreads();
    unsigned any = 0;
#pragma unroll
    for (int w = 0; w < NW; w++) any |= (La[ty][w] & Lb[tx][w]);
    g_Ap[(size_t)(blockIdx.y * 32 + ty) * KP + blockIdx.x * 32 + tx] = any ? 1.0f : 0.0f;
}

// ---------------- pooled degree ----------------
__global__ void degp_kernel() {
    int i = blockIdx.x, t = threadIdx.x;
    __shared__ float red[256];
    float s = 0.f;
    for (int j = t; j < KP; j += 256) s += g_Ap[(size_t)i * KP + j];
    red[t] = s;
    __syncthreads();
    for (int st = 128; st > 0; st >>= 1) { if (t < st) red[t] += red[t + st]; __syncthreads(); }
    if (t == 0) g_dinvp[i] = rsqrtf(red[0]);
}

// ---------------- final deterministic reduce ----------------
__global__ void __launch_bounds__(1024) finalize_kernel(float* out) {
    __shared__ float red[1024];
    int t = threadIdx.x;
    float v = (g_cgs[t] + g_cgs[t + 1024] + g_cgt[t] + g_cgt[t + 1024]) * (1.0f / 2048.0f)
            + (g_cps[t] + g_cpt[t]) * (1.0f / 1024.0f);
    red[t] = v;
    __syncthreads();
    for (int s = 512; s > 0; s >>= 1) { if (t < s) red[t] += red[t + s]; __syncthreads(); }
    if (t == 0) out[0] = red[0];
}

// ---------------- launch ----------------
extern "C" void kernel_launch(void* const* d_in, const int* in_sizes, int n_in,
                              void* d_out, int out_size) {
    const float* fs  = (const float*)d_in[0];
    const float* ft  = (const float*)d_in[1];
    const float* We  = (const float*)d_in[2];
    const float* be  = (const float*)d_in[3];
    const float* Wg  = (const float*)d_in[4];
    const float* bg  = (const float*)d_in[5];
    const float* Wp  = (const float*)d_in[6];
    const float* bp  = (const float*)d_in[7];
    const float* Wgp = (const float*)d_in[8];
    const float* bgp = (const float*)d_in[9];
    float* out = (float*)d_out;

    // embed both branches + rownorm
    mma_nn<<<dim3(2, 64), 128>>>(0, CD, fs, ft, We, be);
    rownorm_kernel<<<2 * NN, 128>>>(0);
    // adjacency bits directly from gram epilogue + degree
    mma_nt<<<dim3(NN / 64, NN / 64), 128>>>(0);
    deg_kernel<<<NN / 256, 256>>>();
    // hop1, hop2 (A from bits; dinv[k] fused into B staging)
    mma_nn<<<dim3(4, NN / 64), 128>>>(1, NN, fs, ft, nullptr, nullptr);
    mma_nn<<<dim3(4, NN / 64), 128>>>(2, NN, fs, ft, nullptr, nullptr);
    // TAGConv linear + l2norm
    mma_nn<<<dim3(2, 64), 128>>>(4, 384, fs, ft, Wg, bg);
    rownorm_kernel<<<2 * NN, 128>>>(1);
    // graph-level NCE (fused tiled LSE)
    mma_nt<<<dim3(NN / 64, NN / 64), 128>>>(1);
    lse_tile<<<dim3(NN / 64, NN / 64), 256>>>(0);
    lse_final<<<NN / 256, 256>>>(0);
    // pooling
    scores_kernel<<<NN / 256, 256>>>(Wp, bp);
    topk_kernel<<<1, 1024>>>();
    gather_kernel<<<dim3(KP, 2), 128>>>();
    ap_kernel<<<dim3(KP / 32, KP / 32), dim3(32, 32)>>>();
    degp_kernel<<<KP, 256>>>();
    // pooled TAGConv (k=1)
    mma_nn<<<dim3(4, KP / 64), 128>>>(3, KP, fs, ft, nullptr, nullptr);
    mma_nn<<<dim3(2, 32), 128>>>(5, 256, fs, ft, Wgp, bgp);
    rownorm_kernel<<<2 * KP, 128>>>(2);
    // pooled NCE
    mma_nt<<<dim3(KP / 64, KP / 64), 128>>>(2);
    lse_tile<<<dim3(KP / 64, KP / 64), 256>>>(1);
    lse_final<<<KP / 256, 256>>>(1);
    // total loss
    finalize_kernel<<<1, 1024>>>(out);
}